// round 16
// baseline (speedup 1.0000x reference)
#include <cuda_runtime.h>
#include <cuda_bf16.h>
#include <cstdint>

#define NPTS 16384
#define DIM  128
#define NQ   16384
#define NV   64

#define BQ    128
#define BN    128
#define QT    (NQ / BQ)        // 128 qtiles
#define PT    (NPTS / BN)      // 128 point tiles
#define TOTT  (QT * PT)        // 16384 tile-units
#define NCTA  304              // 2 x 152 SMs (GB300)
#define EPS   0.75f
#define CAP   3072

// ---------------- device globals ----------------
__device__ __nv_bfloat16 g_pb[NPTS * DIM];
__device__ float         g_psq[NPTS];
__device__ unsigned long long g_win[NQ];
__device__ int           g_done[QT];

// ---------------- SMEM layout (bytes) ----------------
#define SM_A     0        // 128x128 bf16, swizzled    (32768)
#define SM_B     32768    // 2 x 32768                 -> 98304
#define SM_PSQ   98304    // 2 x 512                   -> 99328
#define SM_CURB  99328    // 128 x u32                 -> 99840
#define SM_CNT   99840    // cnt + gather flag         -> 99856
#define SM_CAND  99856    // CAP x u32 (12288)         -> 112144
#define SM_TOTAL 112144

// ---------------- helpers ----------------
__device__ __forceinline__ uint32_t smem_u32(const void* p) {
    uint32_t a;
    asm("{ .reg .u64 t; cvta.to.shared.u64 t, %1; cvt.u32.u64 %0, t; }" : "=r"(a) : "l"(p));
    return a;
}
__device__ __forceinline__ unsigned toOrd(float f) {
    unsigned u = __float_as_uint(f);
    return (u & 0x80000000u) ? ~u : (u | 0x80000000u);
}
__device__ __forceinline__ float fromOrd(unsigned u) {
    unsigned v = (u & 0x80000000u) ? (u & 0x7fffffffu) : ~u;
    return __uint_as_float(v);
}

#define CP_ASYNC16(d, s) asm volatile("cp.async.cg.shared.global [%0], [%1], 16;" :: "r"(d), "l"(s) : "memory")

#define LDSM4(r0, r1, r2, r3, addr) \
    asm volatile("ldmatrix.sync.aligned.m8n8.x4.shared.b16 {%0,%1,%2,%3}, [%4];" \
                 : "=r"(r0), "=r"(r1), "=r"(r2), "=r"(r3) : "r"(addr))

// accumulate form: D = A*B + D
#define MMA16816(c, a, b) \
    asm volatile("mma.sync.aligned.m16n8k16.row.col.f32.bf16.bf16.f32 " \
                 "{%0,%1,%2,%3}, {%4,%5,%6,%7}, {%8,%9}, {%0,%1,%2,%3};" \
                 : "+f"((c)[0]), "+f"((c)[1]), "+f"((c)[2]), "+f"((c)[3]) \
                 : "r"((a)[0]), "r"((a)[1]), "r"((a)[2]), "r"((a)[3]), \
                   "r"((b)[0]), "r"((b)[1]))

// init form: D = A*B + 0
#define MMA16816_INIT(c, a, b, z) \
    asm volatile("mma.sync.aligned.m16n8k16.row.col.f32.bf16.bf16.f32 " \
                 "{%0,%1,%2,%3}, {%4,%5,%6,%7}, {%8,%9}, {%10,%10,%10,%10};" \
                 : "=f"((c)[0]), "=f"((c)[1]), "=f"((c)[2]), "=f"((c)[3]) \
                 : "r"((a)[0]), "r"((a)[1]), "r"((a)[2]), "r"((a)[3]), \
                   "r"((b)[0]), "r"((b)[1]), "f"(z))

__device__ __forceinline__ uint4 pack_bf16x8(float4 a, float4 b) {
    __nv_bfloat162 p0 = __floats2bfloat162_rn(a.x, a.y);
    __nv_bfloat162 p1 = __floats2bfloat162_rn(a.z, a.w);
    __nv_bfloat162 p2 = __floats2bfloat162_rn(b.x, b.y);
    __nv_bfloat162 p3 = __floats2bfloat162_rn(b.z, b.w);
    uint4 o;
    o.x = *reinterpret_cast<uint32_t*>(&p0);
    o.y = *reinterpret_cast<uint32_t*>(&p1);
    o.z = *reinterpret_cast<uint32_t*>(&p2);
    o.w = *reinterpret_cast<uint32_t*>(&p3);
    return o;
}

// ---------------- kernel 0: points fp32 -> bf16 + |p|^2 + init ----------------
__global__ void cvt_kernel(const float* __restrict__ pts) {
    int i = blockIdx.x * blockDim.x + threadIdx.x;   // 8-elt chunk index
    if (i < NQ) g_win[i] = ~0ull;
    if (i < QT) g_done[i] = 0;
    const float4* src = (const float4*)pts;
    float4 a = src[(size_t)i * 2], b = src[(size_t)i * 2 + 1];
    reinterpret_cast<uint4*>(g_pb)[i] = pack_bf16x8(a, b);
    float s = a.x * a.x + a.y * a.y + a.z * a.z + a.w * a.w
            + b.x * b.x + b.y * b.y + b.z * b.z + b.w * b.w;
    #pragma unroll
    for (int off = 8; off; off >>= 1) s += __shfl_xor_sync(0xffffffffu, s, off);
    if ((i & 15) == 0) g_psq[i >> 4] = s;
}

// ---------------- B-tile producer ----------------
__device__ __forceinline__ void issue_tile(uint32_t sb, int ptile, int b, int tid) {
    const char* srcB = (const char*)(g_pb + (size_t)ptile * BN * DIM);
    #pragma unroll
    for (int it = 0; it < 8; it++) {
        int idx = it * 256 + tid;
        int r = idx >> 4, c = idx & 15;
        CP_ASYNC16(sb + SM_B + b * 32768 + r * 256 + ((c ^ (r & 7)) << 4),
                   srcB + (size_t)r * 256 + c * 16);
    }
    if (tid < 32)
        CP_ASYNC16(sb + SM_PSQ + b * 512 + tid * 16,
                   (const char*)(g_psq + (size_t)ptile * BN) + tid * 16);
}

// ---------------- main kernel: HMMA NN + fused gather ----------------
__global__ __launch_bounds__(256, 2)
void nn_main(const float* __restrict__ points,
             const float* __restrict__ points_q,
             const float* __restrict__ values,
             float* __restrict__ out) {
    extern __shared__ char smem[];
    const uint32_t sb = smem_u32(smem);
    unsigned* curB = (unsigned*)(smem + SM_CURB);
    unsigned* cntP = (unsigned*)(smem + SM_CNT);
    int*      gFlag = (int*)(smem + SM_CNT + 4);
    unsigned* cand = (unsigned*)(smem + SM_CAND);
    const float2* psqS2 = (const float2*)(smem + SM_PSQ);

    const int tid = threadIdx.x, wid = tid >> 5, lane = tid & 31;
    // warp tile 32(M) x 64(N): 4 m-warps x 2 n-warps
    const int warpM = (wid >> 1) * 32, warpN = (wid & 1) * 64;

    // ldmatrix address precompute
    uint32_t aB[2], aX[2];
    #pragma unroll
    for (int m = 0; m < 2; m++) {
        int r = warpM + m * 16 + (lane & 15);
        aB[m] = sb + SM_A + r * 256;
        aX[m] = r & 7;
    }
    const int aHi = lane >> 4;
    uint32_t bOf[4], bX[4];
    #pragma unroll
    for (int p = 0; p < 4; p++) {
        int n = warpN + p * 16 + (lane & 7) + ((lane >> 4) << 3);
        bOf[p] = n * 256;
        bX[p] = n & 7;
    }
    const int bHi = (lane >> 3) & 1;
    const int rLane = lane >> 2;
    const int cLane = (lane & 3) * 2;
    const int quadLead = ((lane & 3) == 0);
    const float fZero = 0.0f;

    // balanced contiguous tile range for this CTA
    int g    = (int)(((long long)blockIdx.x * TOTT) / NCTA);
    int gEnd = (int)(((long long)(blockIdx.x + 1) * TOTT) / NCTA);

    while (g < gEnd) {
        const int q = g >> 7;
        const int segEnd = min(gEnd, (q + 1) << 7);
        const int nt = segEnd - g;
        const int qBase = q * BQ;

        if (tid < BQ) curB[tid] = toOrd(3.0e38f);
        if (tid == 0) *cntP = 0;

        // A tile: read fp32 queries, convert to bf16, store swizzled
        {
            const float4* qf4 = (const float4*)(points_q + (size_t)qBase * DIM);
            #pragma unroll
            for (int it = 0; it < 8; it++) {
                int idx = it * 256 + tid;
                int r = idx >> 4, c = idx & 15;
                float4 a = qf4[(size_t)r * 32 + c * 2];
                float4 b = qf4[(size_t)r * 32 + c * 2 + 1];
                *(uint4*)(smem + SM_A + r * 256 + ((c ^ (r & 7)) << 4)) = pack_bf16x8(a, b);
            }
        }
        issue_tile(sb, (g & 127), 0, tid);
        asm volatile("cp.async.commit_group;" ::: "memory");
        asm volatile("cp.async.wait_group 0;" ::: "memory");
        __syncthreads();

        for (int i = 0; i < nt; i++) {
            const int b = i & 1;
            const int ptile = (g + i) & 127;
            if (i + 1 < nt) {
                issue_tile(sb, (g + i + 1) & 127, b ^ 1, tid);
                asm volatile("cp.async.commit_group;" ::: "memory");
            }

            float acc[2][8][4];
            const uint32_t bBase = sb + SM_B + b * 32768;
            #pragma unroll
            for (int ks = 0; ks < 8; ks++) {
                uint32_t af[2][4], bf[4][4];
                #pragma unroll
                for (int m = 0; m < 2; m++)
                    LDSM4(af[m][0], af[m][1], af[m][2], af[m][3],
                          aB[m] + ((((ks << 1) + aHi) ^ aX[m]) << 4));
                #pragma unroll
                for (int p = 0; p < 4; p++)
                    LDSM4(bf[p][0], bf[p][1], bf[p][2], bf[p][3],
                          bBase + bOf[p] + ((((ks << 1) + bHi) ^ bX[p]) << 4));
                if (ks == 0) {
                    #pragma unroll
                    for (int m = 0; m < 2; m++)
                        #pragma unroll
                        for (int n = 0; n < 8; n++)
                            MMA16816_INIT(acc[m][n], af[m], &bf[n >> 1][(n & 1) * 2], fZero);
                } else {
                    #pragma unroll
                    for (int m = 0; m < 2; m++)
                        #pragma unroll
                        for (int n = 0; n < 8; n++)
                            MMA16816(acc[m][n], af[m], &bf[n >> 1][(n & 1) * 2]);
                }
            }

            // ---- pass 1: per-row tile min, quad-reduced, guarded atomics ----
            float ps[8][2];
            #pragma unroll
            for (int n = 0; n < 8; n++) {
                int col = warpN + n * 8 + cLane;
                float2 v = psqS2[(b * 128 + col) >> 1];
                ps[n][0] = v.x; ps[n][1] = v.y;
            }
            float rowMin[2][2];
            #pragma unroll
            for (int m = 0; m < 2; m++)
                #pragma unroll
                for (int h = 0; h < 2; h++) {
                    float mv = 3.0e38f;
                    #pragma unroll
                    for (int n = 0; n < 8; n++) {
                        mv = fminf(mv, fmaf(acc[m][n][h * 2 + 0], -2.0f, ps[n][0]));
                        mv = fminf(mv, fmaf(acc[m][n][h * 2 + 1], -2.0f, ps[n][1]));
                    }
                    rowMin[m][h] = mv;
                    float qv = mv;
                    qv = fminf(qv, __shfl_xor_sync(0xffffffffu, qv, 1));
                    qv = fminf(qv, __shfl_xor_sync(0xffffffffu, qv, 2));
                    if (quadLead) {
                        int r = warpM + m * 16 + rLane + h * 8;
                        unsigned o = toOrd(qv);
                        if (o < curB[r]) atomicMin(&curB[r], o);
                    }
                }

            // ---- pass 2 BEFORE barrier: stale lim only adds candidates ----
            #pragma unroll
            for (int m = 0; m < 2; m++)
                #pragma unroll
                for (int h = 0; h < 2; h++) {
                    int r = warpM + m * 16 + rLane + h * 8;
                    float lim = fromOrd(curB[r]) + EPS;
                    if (rowMin[m][h] < lim) {
                        #pragma unroll
                        for (int n = 0; n < 8; n++)
                            #pragma unroll
                            for (int j = 0; j < 2; j++) {
                                float s = fmaf(acc[m][n][h * 2 + j], -2.0f, ps[n][j]);
                                if (s < lim) {
                                    unsigned slot = atomicAdd(cntP, 1u);
                                    unsigned nIdx = (unsigned)(ptile * BN + warpN + n * 8 + cLane + j);
                                    if (slot < CAP) cand[slot] = ((unsigned)r << 14) | nIdx;
                                }
                            }
                    }
                }

            // ---- single barrier per tile (last op): next B ready + buffer recycle ----
            asm volatile("cp.async.wait_group 0;" ::: "memory");
            __syncthreads();
        }

        // ---- exact fp32 rescore -> global win (16-lane groups, masked) ----
        unsigned total = *cntP;
        if (total > CAP) total = CAP;
        {
            const int grp = lane >> 4, sl = lane & 15;
            const unsigned gmask = 0xFFFFu << (grp * 16);
            for (unsigned c = (unsigned)(wid * 2 + grp); c < total; c += 16) {
                unsigned pk = cand[c];
                int qr = pk >> 14, n = pk & 16383;
                const float4* qp = (const float4*)(points_q + (size_t)(qBase + qr) * DIM);
                const float4* pp = (const float4*)(points + (size_t)n * DIM);
                float4 q0 = qp[sl], q1 = qp[sl + 16];
                float4 p0 = pp[sl], p1 = pp[sl + 16];
                float d = q0.x * p0.x + q0.y * p0.y + q0.z * p0.z + q0.w * p0.w
                        + q1.x * p1.x + q1.y * p1.y + q1.z * p1.z + q1.w * p1.w;
                #pragma unroll
                for (int o = 8; o; o >>= 1) d += __shfl_xor_sync(gmask, d, o);
                if (sl == 0) {
                    float s = fmaf(d, -2.0f, g_psq[n]);
                    unsigned long long key = ((unsigned long long)toOrd(s) << 32) | (unsigned)n;
                    atomicMin(&g_win[qBase + qr], key);
                }
            }
        }
        __syncthreads();

        // ---- fused gather: last CTA to finish this qtile gathers it ----
        if (tid == 0) {
            __threadfence();                               // g_win mins visible before count
            int old = atomicAdd(&g_done[q], nt);
            *gFlag = (old + nt == PT);
        }
        __syncthreads();
        if (*gFlag) {
            for (int i2 = tid; i2 < BQ * 16; i2 += 256) {
                int qr = i2 >> 4, c4 = i2 & 15;
                unsigned long long w = __ldcg(&g_win[qBase + qr]);   // L2 read (coherent w/ atomics)
                unsigned idx = (unsigned)(w & 0xFFFFFFFFu);
                *(float4*)(out + (size_t)(qBase + qr) * NV + c4 * 4) =
                    *(const float4*)(values + (size_t)idx * NV + c4 * 4);
            }
        }
        __syncthreads();   // cand/cnt/gFlag reuse safety for next segment

        g = segEnd;
    }
}

// ---------------- launch ----------------
extern "C" void kernel_launch(void* const* d_in, const int* in_sizes, int n_in,
                              void* d_out, int out_size) {
    const float* points   = (const float*)d_in[0];   // [16384,128]
    const float* values   = (const float*)d_in[1];   // [16384,64]
    const float* points_q = (const float*)d_in[2];   // [16384,128]
    float* out = (float*)d_out;

    cvt_kernel<<<(NPTS * DIM / 8) / 256, 256>>>(points);

    cudaFuncSetAttribute(nn_main, cudaFuncAttributeMaxDynamicSharedMemorySize, SM_TOTAL);
    nn_main<<<NCTA, 256, SM_TOTAL>>>(points, points_q, values, out);
    (void)in_sizes; (void)n_in; (void)out_size;
}

// round 17
// speedup vs baseline: 1.1636x; 1.1636x over previous
#include <cuda_runtime.h>
#include <cuda_bf16.h>
#include <cstdint>

#define NPTS 16384
#define DIM  128
#define NQ   16384
#define NV   64

#define BQ    128
#define BN    128
#define QT    (NQ / BQ)        // 128 qtiles
#define PT    (NPTS / BN)      // 128 point tiles
#define TOTT  (QT * PT)        // 16384 tile-units
#define NCTA  304              // 2 x 152 SMs (GB300)
#define EPS   0.75f
#define CAP   3072

// ---------------- device globals ----------------
__device__ __nv_bfloat16 g_pb[NPTS * DIM];
__device__ float         g_psq[NPTS];
__device__ unsigned long long g_win[NQ];

// ---------------- SMEM layout (bytes) ----------------
#define SM_A     0        // 128x128 bf16, swizzled    (32768)
#define SM_B     32768    // 2 x 32768                 -> 98304
#define SM_PSQ   98304    // 2 x 512                   -> 99328
#define SM_CURB  99328    // 128 x u32                 -> 99840
#define SM_CNT   99840    //                           -> 99856
#define SM_CAND  99856    // CAP x u32 (12288)         -> 112144
#define SM_TOTAL 112144

// ---------------- helpers ----------------
__device__ __forceinline__ uint32_t smem_u32(const void* p) {
    uint32_t a;
    asm("{ .reg .u64 t; cvta.to.shared.u64 t, %1; cvt.u32.u64 %0, t; }" : "=r"(a) : "l"(p));
    return a;
}
__device__ __forceinline__ unsigned toOrd(float f) {
    unsigned u = __float_as_uint(f);
    return (u & 0x80000000u) ? ~u : (u | 0x80000000u);
}
__device__ __forceinline__ float fromOrd(unsigned u) {
    unsigned v = (u & 0x80000000u) ? (u & 0x7fffffffu) : ~u;
    return __uint_as_float(v);
}

#define CP_ASYNC16(d, s) asm volatile("cp.async.cg.shared.global [%0], [%1], 16;" :: "r"(d), "l"(s) : "memory")

#define LDSM4(r0, r1, r2, r3, addr) \
    asm volatile("ldmatrix.sync.aligned.m8n8.x4.shared.b16 {%0,%1,%2,%3}, [%4];" \
                 : "=r"(r0), "=r"(r1), "=r"(r2), "=r"(r3) : "r"(addr))

// accumulate form: D = A*B + D
#define MMA16816(c, a, b) \
    asm volatile("mma.sync.aligned.m16n8k16.row.col.f32.bf16.bf16.f32 " \
                 "{%0,%1,%2,%3}, {%4,%5,%6,%7}, {%8,%9}, {%0,%1,%2,%3};" \
                 : "+f"((c)[0]), "+f"((c)[1]), "+f"((c)[2]), "+f"((c)[3]) \
                 : "r"((a)[0]), "r"((a)[1]), "r"((a)[2]), "r"((a)[3]), \
                   "r"((b)[0]), "r"((b)[1]))

// init form: D = A*B + 0 (C = zero reg, D written fresh — no per-tile zero MOVs)
#define MMA16816_INIT(c, a, b, z) \
    asm volatile("mma.sync.aligned.m16n8k16.row.col.f32.bf16.bf16.f32 " \
                 "{%0,%1,%2,%3}, {%4,%5,%6,%7}, {%8,%9}, {%10,%10,%10,%10};" \
                 : "=f"((c)[0]), "=f"((c)[1]), "=f"((c)[2]), "=f"((c)[3]) \
                 : "r"((a)[0]), "r"((a)[1]), "r"((a)[2]), "r"((a)[3]), \
                   "r"((b)[0]), "r"((b)[1]), "f"(z))

// pack 8 fp32 (two float4) -> uint4 of bf16
__device__ __forceinline__ uint4 pack_bf16x8(float4 a, float4 b) {
    __nv_bfloat162 p0 = __floats2bfloat162_rn(a.x, a.y);
    __nv_bfloat162 p1 = __floats2bfloat162_rn(a.z, a.w);
    __nv_bfloat162 p2 = __floats2bfloat162_rn(b.x, b.y);
    __nv_bfloat162 p3 = __floats2bfloat162_rn(b.z, b.w);
    uint4 o;
    o.x = *reinterpret_cast<uint32_t*>(&p0);
    o.y = *reinterpret_cast<uint32_t*>(&p1);
    o.z = *reinterpret_cast<uint32_t*>(&p2);
    o.w = *reinterpret_cast<uint32_t*>(&p3);
    return o;
}

// ---------------- kernel 0: points fp32 -> bf16 + |p|^2 + win init ----------------
__global__ void cvt_kernel(const float* __restrict__ pts) {
    int i = blockIdx.x * blockDim.x + threadIdx.x;   // 8-elt chunk index
    if (i < NQ) g_win[i] = ~0ull;
    const float4* src = (const float4*)pts;
    float4 a = src[(size_t)i * 2], b = src[(size_t)i * 2 + 1];
    reinterpret_cast<uint4*>(g_pb)[i] = pack_bf16x8(a, b);
    float s = a.x * a.x + a.y * a.y + a.z * a.z + a.w * a.w
            + b.x * b.x + b.y * b.y + b.z * b.z + b.w * b.w;
    #pragma unroll
    for (int off = 8; off; off >>= 1) s += __shfl_xor_sync(0xffffffffu, s, off);
    if ((i & 15) == 0) g_psq[i >> 4] = s;
}

// ---------------- B-tile producer ----------------
__device__ __forceinline__ void issue_tile(uint32_t sb, int ptile, int b, int tid) {
    const char* srcB = (const char*)(g_pb + (size_t)ptile * BN * DIM);
    #pragma unroll
    for (int it = 0; it < 8; it++) {
        int idx = it * 256 + tid;
        int r = idx >> 4, c = idx & 15;
        CP_ASYNC16(sb + SM_B + b * 32768 + r * 256 + ((c ^ (r & 7)) << 4),
                   srcB + (size_t)r * 256 + c * 16);
    }
    if (tid < 32)
        CP_ASYNC16(sb + SM_PSQ + b * 512 + tid * 16,
                   (const char*)(g_psq + (size_t)ptile * BN) + tid * 16);
}

// ---------------- main kernel: HMMA NN, balanced tile-range partition ----------------
__global__ __launch_bounds__(256, 2)
void nn_main(const float* __restrict__ points,
             const float* __restrict__ points_q,
             float* __restrict__ out) {
    extern __shared__ char smem[];
    const uint32_t sb = smem_u32(smem);
    unsigned* curB = (unsigned*)(smem + SM_CURB);
    unsigned* cntP = (unsigned*)(smem + SM_CNT);
    unsigned* cand = (unsigned*)(smem + SM_CAND);
    const float2* psqS2 = (const float2*)(smem + SM_PSQ);

    const int tid = threadIdx.x, wid = tid >> 5, lane = tid & 31;
    // warp tile 32(M) x 64(N): 4 m-warps x 2 n-warps
    const int warpM = (wid >> 1) * 32, warpN = (wid & 1) * 64;

    // ldmatrix address precompute
    uint32_t aB[2], aX[2];
    #pragma unroll
    for (int m = 0; m < 2; m++) {
        int r = warpM + m * 16 + (lane & 15);
        aB[m] = sb + SM_A + r * 256;
        aX[m] = r & 7;
    }
    const int aHi = lane >> 4;
    uint32_t bOf[4], bX[4];
    #pragma unroll
    for (int p = 0; p < 4; p++) {
        int n = warpN + p * 16 + (lane & 7) + ((lane >> 4) << 3);
        bOf[p] = n * 256;
        bX[p] = n & 7;
    }
    const int bHi = (lane >> 3) & 1;
    const int rLane = lane >> 2;
    const int cLane = (lane & 3) * 2;
    const int quadLead = ((lane & 3) == 0);
    const float fZero = 0.0f;

    // balanced contiguous tile range for this CTA
    int g    = (int)(((long long)blockIdx.x * TOTT) / NCTA);
    int gEnd = (int)(((long long)(blockIdx.x + 1) * TOTT) / NCTA);

    while (g < gEnd) {
        const int q = g >> 7;
        const int segEnd = min(gEnd, (q + 1) << 7);
        const int nt = segEnd - g;
        const int qBase = q * BQ;

        if (tid < BQ) curB[tid] = toOrd(3.0e38f);
        if (tid == 0) *cntP = 0;

        // A tile: read fp32 queries, convert to bf16, store swizzled
        {
            const float4* qf4 = (const float4*)(points_q + (size_t)qBase * DIM);
            #pragma unroll
            for (int it = 0; it < 8; it++) {
                int idx = it * 256 + tid;
                int r = idx >> 4, c = idx & 15;
                float4 a = qf4[(size_t)r * 32 + c * 2];
                float4 b = qf4[(size_t)r * 32 + c * 2 + 1];
                *(uint4*)(smem + SM_A + r * 256 + ((c ^ (r & 7)) << 4)) = pack_bf16x8(a, b);
            }
        }
        issue_tile(sb, (g & 127), 0, tid);
        asm volatile("cp.async.commit_group;" ::: "memory");
        asm volatile("cp.async.wait_group 0;" ::: "memory");
        __syncthreads();

        for (int i = 0; i < nt; i++) {
            const int b = i & 1;
            const int ptile = (g + i) & 127;
            if (i + 1 < nt) {
                issue_tile(sb, (g + i + 1) & 127, b ^ 1, tid);
                asm volatile("cp.async.commit_group;" ::: "memory");
            }

            float acc[2][8][4];
            const uint32_t bBase = sb + SM_B + b * 32768;
            #pragma unroll
            for (int ks = 0; ks < 8; ks++) {
                uint32_t af[2][4], bf[4][4];
                #pragma unroll
                for (int m = 0; m < 2; m++)
                    LDSM4(af[m][0], af[m][1], af[m][2], af[m][3],
                          aB[m] + ((((ks << 1) + aHi) ^ aX[m]) << 4));
                #pragma unroll
                for (int p = 0; p < 4; p++)
                    LDSM4(bf[p][0], bf[p][1], bf[p][2], bf[p][3],
                          bBase + bOf[p] + ((((ks << 1) + bHi) ^ bX[p]) << 4));
                if (ks == 0) {
                    #pragma unroll
                    for (int m = 0; m < 2; m++)
                        #pragma unroll
                        for (int n = 0; n < 8; n++)
                            MMA16816_INIT(acc[m][n], af[m], &bf[n >> 1][(n & 1) * 2], fZero);
                } else {
                    #pragma unroll
                    for (int m = 0; m < 2; m++)
                        #pragma unroll
                        for (int n = 0; n < 8; n++)
                            MMA16816(acc[m][n], af[m], &bf[n >> 1][(n & 1) * 2]);
                }
            }

            // ---- pass 1: per-row tile min, quad-reduced, guarded atomics ----
            float ps[8][2];
            #pragma unroll
            for (int n = 0; n < 8; n++) {
                int col = warpN + n * 8 + cLane;           // even by construction
                float2 v = psqS2[(b * 128 + col) >> 1];
                ps[n][0] = v.x; ps[n][1] = v.y;
            }
            float rowMin[2][2];
            #pragma unroll
            for (int m = 0; m < 2; m++)
                #pragma unroll
                for (int h = 0; h < 2; h++) {
                    float mv = 3.0e38f;
                    #pragma unroll
                    for (int n = 0; n < 8; n++) {
                        mv = fminf(mv, fmaf(acc[m][n][h * 2 + 0], -2.0f, ps[n][0]));
                        mv = fminf(mv, fmaf(acc[m][n][h * 2 + 1], -2.0f, ps[n][1]));
                    }
                    rowMin[m][h] = mv;
                    float qv = mv;
                    qv = fminf(qv, __shfl_xor_sync(0xffffffffu, qv, 1));
                    qv = fminf(qv, __shfl_xor_sync(0xffffffffu, qv, 2));
                    if (quadLead) {
                        int r = warpM + m * 16 + rLane + h * 8;
                        unsigned o = toOrd(qv);
                        if (o < curB[r]) atomicMin(&curB[r], o);   // guarded: steady-state no-op
                    }
                }

            // ---- single barrier per tile: curB visibility + next B ready ----
            asm volatile("cp.async.wait_group 0;" ::: "memory");
            __syncthreads();

            // ---- pass 2: push margin candidates (gated, rare) ----
            #pragma unroll
            for (int m = 0; m < 2; m++)
                #pragma unroll
                for (int h = 0; h < 2; h++) {
                    int r = warpM + m * 16 + rLane + h * 8;
                    float lim = fromOrd(curB[r]) + EPS;
                    if (rowMin[m][h] < lim) {
                        #pragma unroll
                        for (int n = 0; n < 8; n++)
                            #pragma unroll
                            for (int j = 0; j < 2; j++) {
                                float s = fmaf(acc[m][n][h * 2 + j], -2.0f, ps[n][j]);
                                if (s < lim) {
                                    unsigned slot = atomicAdd(cntP, 1u);
                                    unsigned nIdx = (unsigned)(ptile * BN + warpN + n * 8 + cLane + j);
                                    if (slot < CAP) cand[slot] = ((unsigned)r << 14) | nIdx;
                                }
                            }
                    }
                }
        }
        __syncthreads();

        // ---- exact fp32 rescore -> global win (16-lane groups, masked) ----
        unsigned total = *cntP;
        if (total > CAP) total = CAP;
        {
            const int grp = lane >> 4, sl = lane & 15;
            const unsigned gmask = 0xFFFFu << (grp * 16);
            for (unsigned c = (unsigned)(wid * 2 + grp); c < total; c += 16) {
                unsigned pk = cand[c];
                int qr = pk >> 14, n = pk & 16383;
                const float4* qp = (const float4*)(points_q + (size_t)(qBase + qr) * DIM);
                const float4* pp = (const float4*)(points + (size_t)n * DIM);
                float4 q0 = qp[sl], q1 = qp[sl + 16];
                float4 p0 = pp[sl], p1 = pp[sl + 16];
                float d = q0.x * p0.x + q0.y * p0.y + q0.z * p0.z + q0.w * p0.w
                        + q1.x * p1.x + q1.y * p1.y + q1.z * p1.z + q1.w * p1.w;
                #pragma unroll
                for (int o = 8; o; o >>= 1) d += __shfl_xor_sync(gmask, d, o);
                if (sl == 0) {
                    float s = fmaf(d, -2.0f, g_psq[n]);
                    unsigned long long key = ((unsigned long long)toOrd(s) << 32) | (unsigned)n;
                    atomicMin(&g_win[qBase + qr], key);
                }
            }
        }
        __syncthreads();   // cand/cnt reuse safety for next segment

        g = segEnd;
    }
}

// ---------------- kernel 2: gather ----------------
__global__ void gather_kernel(const float* __restrict__ values, float* __restrict__ out) {
    int i = blockIdx.x * blockDim.x + threadIdx.x;   // float4 index
    int q = i >> 4, c4 = i & 15;
    unsigned idx = (unsigned)(g_win[q] & 0xFFFFFFFFu);
    *(float4*)(out + (size_t)q * NV + c4 * 4) =
        *(const float4*)(values + (size_t)idx * NV + c4 * 4);
}

// ---------------- launch ----------------
extern "C" void kernel_launch(void* const* d_in, const int* in_sizes, int n_in,
                              void* d_out, int out_size) {
    const float* points   = (const float*)d_in[0];   // [16384,128]
    const float* values   = (const float*)d_in[1];   // [16384,64]
    const float* points_q = (const float*)d_in[2];   // [16384,128]
    float* out = (float*)d_out;

    cvt_kernel<<<(NPTS * DIM / 8) / 256, 256>>>(points);

    cudaFuncSetAttribute(nn_main, cudaFuncAttributeMaxDynamicSharedMemorySize, SM_TOTAL);
    nn_main<<<NCTA, 256, SM_TOTAL>>>(points, points_q, out);

    gather_kernel<<<(NQ * 16) / 256, 256>>>(values, out);
    (void)in_sizes; (void)n_in; (void)out_size;
}